// round 14
// baseline (speedup 1.0000x reference)
#include <cuda_runtime.h>

// LIF scan: mem = 0.25*mem + x[t]; spk = (mem >= 1.0); mem -= spk.
// Shape [T=100, 32, 16384] fp32. One thread owns 4 neurons (float4),
// accumulator in registers, coalesced streaming loads/stores per timestep.
//
// vs R13 (best, 71.3us): identical structure (unroll 2, 512x256), adding
// ONLY __ldcs/__stcs. One-touch 419MB stream through 126MB L2: evict-first
// policy stops the write-allocate stream from displacing in-flight read
// sectors. Clean single-variable A/B (R8 had these hints confounded with
// unroll-10).

#define T_STEPS 100
#define NEURONS (32 * 16384)          // 524288
#define VEC4    (NEURONS / 4)         // 131072 float4 lanes per timestep

__global__ __launch_bounds__(256) void lif_kernel(const float4* __restrict__ x,
                                                  float4* __restrict__ out) {
    const int i = blockIdx.x * blockDim.x + threadIdx.x;  // 0..VEC4-1

    float mx = 0.f, my = 0.f, mz = 0.f, mw = 0.f;

    const float4* __restrict__ xp = x + i;
    float4* __restrict__ op = out + i;

#pragma unroll 2
    for (int t = 0; t < T_STEPS; ++t) {
        const float4 xt = __ldcs(&xp[(long)t * VEC4]);

        mx = fmaf(0.25f, mx, xt.x);
        my = fmaf(0.25f, my, xt.y);
        mz = fmaf(0.25f, mz, xt.z);
        mw = fmaf(0.25f, mw, xt.w);

        const float sx = (mx >= 1.0f) ? 1.0f : 0.0f;
        const float sy = (my >= 1.0f) ? 1.0f : 0.0f;
        const float sz = (mz >= 1.0f) ? 1.0f : 0.0f;
        const float sw = (mw >= 1.0f) ? 1.0f : 0.0f;

        mx -= sx;
        my -= sy;
        mz -= sz;
        mw -= sw;

        float4 s;
        s.x = sx; s.y = sy; s.z = sz; s.w = sw;
        __stcs(&op[(long)t * VEC4], s);
    }
}

extern "C" void kernel_launch(void* const* d_in, const int* in_sizes, int n_in,
                              void* d_out, int out_size) {
    const float4* x = (const float4*)d_in[0];
    float4* out = (float4*)d_out;

    const int threads = 256;
    const int blocks = VEC4 / threads;  // 512
    lif_kernel<<<blocks, threads>>>(x, out);
}

// round 16
// speedup vs baseline: 1.1728x; 1.1728x over previous
#include <cuda_runtime.h>

// LIF scan: mem = 0.25*mem + x[t]; spk = (mem >= 1.0); mem -= spk.
// Shape [T=100, 32, 16384] fp32. One thread owns 4 neurons (float4),
// accumulator in registers, coalesced streaming loads/stores per timestep.
//
// FINAL (= R13, best bench 71.3us). Exhaustive A/B ledger:
//   vector width: float4 > float2            (R4)
//   load batching: unroll2 >= unroll4 > 10   (R13/R3/R8)
//   launch shape: 512x256 > 1024x128         (R10)
//   cache hints: default >> __ldcs/__stcs    (R14: evict-first defeats
//                L2 writeback coalescing on sm_103a)
// Bound: compulsory 419MB 1:1 R/W stream at the ~5.8TB/s mixed HBM
// ceiling; remaining gap to 8TB/s spec is R/W turnaround, not kernel.
// (R15 was an infra failure — resubmitting unchanged for the
// confirmation re-bench.)

#define T_STEPS 100
#define NEURONS (32 * 16384)          // 524288
#define VEC4    (NEURONS / 4)         // 131072 float4 lanes per timestep

__global__ __launch_bounds__(256) void lif_kernel(const float4* __restrict__ x,
                                                  float4* __restrict__ out) {
    const int i = blockIdx.x * blockDim.x + threadIdx.x;  // 0..VEC4-1

    float mx = 0.f, my = 0.f, mz = 0.f, mw = 0.f;

    const float4* __restrict__ xp = x + i;
    float4* __restrict__ op = out + i;

#pragma unroll 2
    for (int t = 0; t < T_STEPS; ++t) {
        const float4 xt = xp[(long)t * VEC4];

        mx = fmaf(0.25f, mx, xt.x);
        my = fmaf(0.25f, my, xt.y);
        mz = fmaf(0.25f, mz, xt.z);
        mw = fmaf(0.25f, mw, xt.w);

        const float sx = (mx >= 1.0f) ? 1.0f : 0.0f;
        const float sy = (my >= 1.0f) ? 1.0f : 0.0f;
        const float sz = (mz >= 1.0f) ? 1.0f : 0.0f;
        const float sw = (mw >= 1.0f) ? 1.0f : 0.0f;

        mx -= sx;
        my -= sy;
        mz -= sz;
        mw -= sw;

        float4 s;
        s.x = sx; s.y = sy; s.z = sz; s.w = sw;
        op[(long)t * VEC4] = s;
    }
}

extern "C" void kernel_launch(void* const* d_in, const int* in_sizes, int n_in,
                              void* d_out, int out_size) {
    const float4* x = (const float4*)d_in[0];
    float4* out = (float4*)d_out;

    const int threads = 256;
    const int blocks = VEC4 / threads;  // 512
    lif_kernel<<<blocks, threads>>>(x, out);
}

// round 17
// speedup vs baseline: 1.2149x; 1.0359x over previous
#include <cuda_runtime.h>

// LIF scan: mem = 0.25*mem + x[t]; spk = (mem >= 1.0); mem -= spk.
// Shape [T=100, 32, 16384] fp32. One thread owns 2 neurons (float2).
//
// R17: decontaminated float2 test. R4 (float2+__ldcs/__stcs) hit 60.5%
// DRAM, but R14's clean A/B showed the hints alone cost ~13.6 DRAM pts
// (72.0 -> 58.4 on identical code). Corrected float2 estimate ~74% — at
// or above R13 (72%, best 71.3us). float2 doubles occupancy (40 -> 80%)
// while unroll 2 keeps bytes-in-flight/SM equal (~28KB). No cache hints.

#define T_STEPS 100
#define NEURONS (32 * 16384)          // 524288
#define VEC2    (NEURONS / 2)         // 262144 float2 lanes per timestep

__global__ __launch_bounds__(256) void lif_kernel(const float2* __restrict__ x,
                                                  float2* __restrict__ out) {
    const int i = blockIdx.x * blockDim.x + threadIdx.x;  // 0..VEC2-1

    float mx = 0.f, my = 0.f;

    const float2* __restrict__ xp = x + i;
    float2* __restrict__ op = out + i;

#pragma unroll 2
    for (int t = 0; t < T_STEPS; ++t) {
        const float2 xt = xp[(long)t * VEC2];

        mx = fmaf(0.25f, mx, xt.x);
        my = fmaf(0.25f, my, xt.y);

        const float sx = (mx >= 1.0f) ? 1.0f : 0.0f;
        const float sy = (my >= 1.0f) ? 1.0f : 0.0f;

        mx -= sx;
        my -= sy;

        float2 s;
        s.x = sx; s.y = sy;
        op[(long)t * VEC2] = s;
    }
}

extern "C" void kernel_launch(void* const* d_in, const int* in_sizes, int n_in,
                              void* d_out, int out_size) {
    const float2* x = (const float2*)d_in[0];
    float2* out = (float2*)d_out;

    const int threads = 256;
    const int blocks = VEC2 / threads;  // 1024
    lif_kernel<<<blocks, threads>>>(x, out);
}